// round 5
// baseline (speedup 1.0000x reference)
#include <cuda_runtime.h>
#include <math.h>

#define NB 16
#define NL 128
#define NH 256
#define ND 300
#define NE 34
#define NA 36

__device__ float d_zx[2][NL][NB][4*NH];
__device__ float d_hidden[NB][NL][2*NH];
__device__ float d_hcur[2][2][NB][NH];
__device__ float d_S [NB][NL][NA];
__device__ float d_T [NB][NL][NA];
__device__ float d_E0[NB][NL][NE];
__device__ unsigned g_cnt2[2*32];   // per-dir arrive counters, 128B apart
__device__ unsigned g_gen2[2*32];   // per-dir generation words

__device__ __forceinline__ float sigf(float x){ return 1.f/(1.f + expf(-x)); }

// packed f32x2 fma: d = a*b + c lanewise on two floats in a u64
__device__ __forceinline__ unsigned long long ffma2(unsigned long long a,
        unsigned long long b, unsigned long long c){
    unsigned long long d;
    asm("fma.rn.f32x2 %0, %1, %2, %3;" : "=l"(d) : "l"(a), "l"(b), "l"(c));
    return d;
}
__device__ __forceinline__ float hsum2(unsigned long long v){
    unsigned lo, hi;
    asm("mov.b64 {%0,%1}, %2;" : "=r"(lo), "=r"(hi) : "l"(v));
    return __uint_as_float(lo) + __uint_as_float(hi);
}
// order-preserving float->uint key (exact; ties stay ties)
__device__ __forceinline__ unsigned ordk(float v){
    unsigned u = __float_as_uint(v);
    return (u & 0x80000000u) ? ~u : (u | 0x80000000u);
}

// ============================================================================
// K1: zx = gather(emb, ids) @ Wih^T + (bih+bhh), both directions fused.
// ============================================================================
__global__ void __launch_bounds__(256) k1_zx(const int* __restrict__ ids,
        const float* __restrict__ emb,
        const float* __restrict__ WihF, const float* __restrict__ WihB,
        const float* __restrict__ bihF, const float* __restrict__ bhhF,
        const float* __restrict__ bihB, const float* __restrict__ bhhB)
{
    __shared__ __align__(16) float As[16][68];
    __shared__ __align__(16) float Bs[16][68];
    __shared__ int ids_s[64];
    const int tid = threadIdx.x;
    const int m0 = blockIdx.y * 64;
    const int n0 = blockIdx.x * 64;
    if (tid < 64) ids_s[tid] = ids[m0 + tid];
    __syncthreads();
    const int lm = tid & 63;
    const int k4 = tid >> 6;
    const int ty = tid >> 4;
    const int tx = tid & 15;
    float acc[4][4];
    #pragma unroll
    for (int i=0;i<4;i++){ acc[i][0]=0.f; acc[i][1]=0.f; acc[i][2]=0.f; acc[i][3]=0.f; }

    for (int kt = 0; kt < 19; kt++) {
        const int k0 = kt*16 + k4*4;
        {
            const int id = ids_s[lm];
            const float* src = emb + (long)id*ND + k0;
            float v0=0.f,v1=0.f,v2=0.f,v3=0.f;
            if (k0 + 3 < ND) { float4 t4 = *(const float4*)src; v0=t4.x;v1=t4.y;v2=t4.z;v3=t4.w; }
            else {
                if (k0+0 < ND) v0 = src[0];
                if (k0+1 < ND) v1 = src[1];
                if (k0+2 < ND) v2 = src[2];
            }
            As[k4*4+0][lm]=v0; As[k4*4+1][lm]=v1; As[k4*4+2][lm]=v2; As[k4*4+3][lm]=v3;
        }
        {
            const int n = n0 + lm;
            const float* wr = (n < 1024) ? (WihF + (long)n*ND) : (WihB + (long)(n-1024)*ND);
            const float* src = wr + k0;
            float v0=0.f,v1=0.f,v2=0.f,v3=0.f;
            if (k0 + 3 < ND) { float4 t4 = *(const float4*)src; v0=t4.x;v1=t4.y;v2=t4.z;v3=t4.w; }
            else {
                if (k0+0 < ND) v0 = src[0];
                if (k0+1 < ND) v1 = src[1];
                if (k0+2 < ND) v2 = src[2];
            }
            Bs[k4*4+0][lm]=v0; Bs[k4*4+1][lm]=v1; Bs[k4*4+2][lm]=v2; Bs[k4*4+3][lm]=v3;
        }
        __syncthreads();
        #pragma unroll
        for (int kk = 0; kk < 16; kk++) {
            const float4 a4 = *(const float4*)&As[kk][ty*4];
            const float4 b4 = *(const float4*)&Bs[kk][tx*4];
            const float av[4] = {a4.x,a4.y,a4.z,a4.w};
            const float bv[4] = {b4.x,b4.y,b4.z,b4.w};
            #pragma unroll
            for (int i=0;i<4;i++){
                #pragma unroll
                for (int jj=0;jj<4;jj++) acc[i][jj] = fmaf(av[i], bv[jj], acc[i][jj]);
            }
        }
        __syncthreads();
    }
    #pragma unroll
    for (int jj=0;jj<4;jj++){
        const int n = n0 + tx*4 + jj;
        const float bias = (n < 1024) ? (bihF[n] + bhhF[n]) : (bihB[n-1024] + bhhB[n-1024]);
        #pragma unroll
        for (int i=0;i<4;i++){
            const int m = m0 + ty*4 + i;
            const int bb = m >> 7, t = m & 127;
            const float v = acc[i][jj] + bias;
            if (n < 1024) d_zx[0][t][bb][n]      = v;
            else          d_zx[1][t][bb][n-1024] = v;
        }
    }
}

// ============================================================================
// K2: persistent BiLSTM. 256 blocks (dir = bx>>7, 2 units each) x 256 threads.
// Per-direction flat barrier (128 arrivals). f32x2 packed dot. h loaded
// directly global->regs (no smem staging).
// ============================================================================
__global__ void __launch_bounds__(256,2) k2_lstm(const float* __restrict__ WhhF,
                                                 const float* __restrict__ WhhB)
{
    __shared__ __align__(16) float W_s[8][260];
    __shared__ float zp[8][16][4];
    const int tid = threadIdx.x;
    const int bx  = blockIdx.x;
    const int dir = bx >> 7;
    const int sub = bx & 127;
    const int u0  = sub * 2;
    const float* Whh = dir ? WhhB : WhhF;

    for (int idx = tid; idx < 8*256; idx += 256){
        const int rl = idx >> 8, k = idx & 255;
        const int g = rl >> 1, uu = rl & 1;
        W_s[rl][k] = Whh[(long)(g*256 + u0 + uu)*256 + k];
    }

    const int bdot = tid & 15;
    const int rp   = (tid >> 4) & 3;   // gate index; rows rp*2, rp*2+1
    const int ks   = tid >> 6;         // 0..3, 64-wide k slice

    float creg = 0.f;
    const int gb = tid & 15, guu = (tid >> 4) & 1;   // gates thread (tid<32)

    const unsigned G0 = *(volatile unsigned*)&g_gen2[dir*32];
    __syncthreads();

    for (unsigned t = 0; t < NL; t++){
        const int xt = dir ? (NL-1-(int)t) : (int)t;
        const int wb = t & 1, rb = 1 - wb;

        float zx4[4];
        if (tid < 32){
            const float* zb = &d_zx[dir][xt][gb][0];
            #pragma unroll
            for (int g=0; g<4; g++) zx4[g] = __ldg(zb + g*256 + u0 + guu);
        }

        unsigned long long a00=0ull, a01=0ull, a10=0ull, a11=0ull;
        if (t > 0){
            const ulonglong2* hp = (const ulonglong2*)&d_hcur[dir][rb][bdot][ks*64];
            const ulonglong2* w0 = (const ulonglong2*)&W_s[rp*2  ][ks*64];
            const ulonglong2* w1 = (const ulonglong2*)&W_s[rp*2+1][ks*64];
            #pragma unroll
            for (int i=0;i<16;i++){
                const ulonglong2 hu = __ldcg(hp + i);
                const ulonglong2 wa = w0[i];
                const ulonglong2 wbv= w1[i];
                a00 = ffma2(hu.x, wa.x,  a00);
                a01 = ffma2(hu.y, wa.y,  a01);
                a10 = ffma2(hu.x, wbv.x, a10);
                a11 = ffma2(hu.y, wbv.y, a11);
            }
        }
        zp[rp*2  ][bdot][ks] = hsum2(a00) + hsum2(a01);
        zp[rp*2+1][bdot][ks] = hsum2(a10) + hsum2(a11);
        __syncthreads();

        if (tid < 32){
            float z[4];
            #pragma unroll
            for (int g=0; g<4; g++){
                const float* q = zp[g*2+guu][gb];
                z[g] = zx4[g] + ((q[0]+q[1]) + (q[2]+q[3]));
            }
            creg = sigf(z[1])*creg + sigf(z[0])*tanhf(z[2]);
            const float h = sigf(z[3])*tanhf(creg);
            const int u = u0 + guu;
            __stcg(&d_hcur[dir][wb][gb][u], h);
            d_hidden[gb][xt][dir*NH + u] = h;
        }
        __syncthreads();

        if (t < NL-1){
            if (tid == 0){
                __threadfence();
                const unsigned want = G0 + t + 1u;
                unsigned* cnt = &g_cnt2[dir*32];
                unsigned* gen = &g_gen2[dir*32];
                const unsigned p = atomicAdd(cnt, 1u);
                if (p == G0*128u + t*128u + 127u){
                    atomicExch(gen, want);
                } else {
                    while ((int)(*(volatile unsigned*)gen - want) < 0) {}
                }
                __threadfence();
            }
            __syncthreads();
        }
    }
}

// ============================================================================
// K3: per-token static decode projections S, T, E0.
// ============================================================================
__global__ void __launch_bounds__(128) k3_pre(const float* __restrict__ Wa,
        const float* __restrict__ We,
        const float* __restrict__ ba, const float* __restrict__ be)
{
    __shared__ __align__(16) float hid_s[8][516];
    const int tid = threadIdx.x;
    const int m0 = blockIdx.x * 8;
    const float* hbase = &d_hidden[0][0][0] + (long)m0 * 512;
    for (int idx = tid; idx < 8*512; idx += 128)
        hid_s[idx >> 9][idx & 511] = hbase[idx];
    __syncthreads();
    const int tok = tid >> 4, slot = tid & 15;
    const int m = m0 + tok;
    const float* hv = hid_s[tok];
    for (int cc = slot; cc < 106; cc += 16){
        float acc = 0.f;
        if (cc < 72){
            const float* wr = Wa + (long)(cc < 36 ? cc : cc-36) * 1092 + (cc < 36 ? 0 : 512);
            #pragma unroll 4
            for (int k = 0; k < 512; k += 4){
                const float4 w4 = *(const float4*)(wr + k);
                const float4 h4 = *(const float4*)(hv + k);
                acc = fmaf(h4.x, w4.x, acc);
                acc = fmaf(h4.y, w4.y, acc);
                acc = fmaf(h4.z, w4.z, acc);
                acc = fmaf(h4.w, w4.w, acc);
            }
            if (cc < 36) { acc += ba[cc]; (&d_S[0][0][0])[(long)m*36 + cc]      = acc; }
            else         {               (&d_T[0][0][0])[(long)m*36 + (cc-36)] = acc; }
        } else {
            const int e = cc - 72;
            const float* wr = We + (long)e * 545;
            #pragma unroll 4
            for (int k = 0; k < 512; k += 4){
                acc = fmaf(hv[k+0], wr[k+0], acc);
                acc = fmaf(hv[k+1], wr[k+1], acc);
                acc = fmaf(hv[k+2], wr[k+2], acc);
                acc = fmaf(hv[k+3], wr[k+3], acc);
            }
            acc += be[e];
            (&d_E0[0][0][0])[(long)m*34 + e] = acc;
        }
    }
}

// ============================================================================
// K4: decode scan, syncless producer/consumer.
// 16 blocks (one per batch) x 160 threads.
//   warp 0      : sequential event scan (independent of arg predictions),
//                 publishes ev_pred[i] via smem flags.
//   tids 32..159: one position j each; spin on flag, no __syncthreads in loop.
// ============================================================================
__global__ void __launch_bounds__(160) k4_scan(const float* __restrict__ Wa,
        const float* __restrict__ We,
        float* __restrict__ evout, float* __restrict__ argout)
{
    __shared__ __align__(16) float Ts [NL][NA];    // 18432 B
    __shared__ float E0s[NL][NE];                  // 17408 B
    __shared__ float Wag1_s[35][36];
    __shared__ float Wag2_s[33][36];
    __shared__ float Weg_s [33][34];
    __shared__ int evf[NL];

    const int tid = threadIdx.x;
    const int b = blockIdx.x;
    const int NT = 160;

    for (int idx = tid; idx < NL*NA; idx += NT) (&Ts[0][0])[idx]  = (&d_T[b][0][0])[idx];
    for (int idx = tid; idx < NL*NE; idx += NT) (&E0s[0][0])[idx] = (&d_E0[b][0][0])[idx];
    for (int idx = tid; idx < 35*36; idx += NT){
        const int k = idx / 36, a = idx % 36;
        Wag1_s[k][a] = Wa[(long)a*1092 + 1024 + k];
    }
    for (int idx = tid; idx < 33*36; idx += NT){
        const int k = idx / 36, a = idx % 36;
        Wag2_s[k][a] = Wa[(long)a*1092 + 1059 + k];
    }
    for (int idx = tid; idx < 33*34; idx += NT){
        const int k = idx / 34, e = idx % 34;
        Weg_s[k][e] = We[(long)e*545 + 512 + k];
    }
    for (int idx = tid; idx < NL; idx += NT) evf[idx] = 0;

    // consumer state loaded before the single sync
    float SG[36];
    const int j = tid - 32;
    if (tid >= 32){
        const float4* sp = (const float4*)&d_S[b][j][0];
        #pragma unroll
        for (int q=0;q<9;q++){
            const float4 v = sp[q];
            SG[q*4+0]=v.x; SG[q*4+1]=v.y; SG[q*4+2]=v.z; SG[q*4+3]=v.w;
        }
    }
    __syncthreads();

    if (tid < 32){
        // ---- producer: event scan ----
        const int lane = tid;
        float gtA = 0.f, gtB = 0.f;
        unsigned long long gtrg = 0ull;
        volatile int* vf = evf;
        for (int i = 0; i < NL; i++){
            const float va = E0s[i][lane] + gtA;
            float vb = -3.0e38f;
            if (lane < 2) vb = E0s[i][32+lane] + gtB;
            evout[((long)b*NL + i)*NE + lane] = va;
            if (lane < 2) evout[((long)b*NL + i)*NE + 32 + lane] = vb;
            const unsigned ka = ordk(va);
            const unsigned m  = __reduce_max_sync(0xffffffffu, ka);
            const unsigned ball = __ballot_sync(0xffffffffu, ka == m);
            const int am0 = __ffs(ball) - 1;             // first max among e=0..31
            float bv = __shfl_sync(0xffffffffu, va, am0);
            int ame = am0;
            const float v32 = __shfl_sync(0xffffffffu, vb, 0);
            const float v33 = __shfl_sync(0xffffffffu, vb, 1);
            if (v32 > bv){ bv = v32; ame = 32; }
            if (v33 > bv){ bv = v33; ame = 33; }
            int ne = 0;
            if (ame > 0 && !((gtrg >> (ame-1)) & 1ull)){ gtrg |= 1ull << (ame-1); ne = 1; }
            if (lane == 0) vf[i] = ame + 1;              // publish (flag word is the data)
            if (ne){
                gtA += Weg_s[ame-1][lane];
                if (lane < 2) gtB += Weg_s[ame-1][32+lane];
            }
        }
    } else {
        // ---- consumers: per-position arg scan, no block syncs ----
        unsigned long long garg = 0ull, gta = 0ull;
        volatile int* vf = evf;
        for (int i = 0; i < NL; i++){
            int f;
            while ((f = vf[i]) == 0) {}
            const int ep = f - 1;
            const float* Ti = &Ts[i][0];
            float* op = argout + (((long)b*NL + i)*NL + j)*NA;
            int am = 0; float bm = -1e30f;
            #pragma unroll
            for (int a4 = 0; a4 < 9; a4++){
                const float v0 = SG[a4*4+0] + Ti[a4*4+0];
                const float v1 = SG[a4*4+1] + Ti[a4*4+1];
                const float v2 = SG[a4*4+2] + Ti[a4*4+2];
                const float v3 = SG[a4*4+3] + Ti[a4*4+3];
                if (v0 > bm){ bm = v0; am = a4*4+0; }
                if (v1 > bm){ bm = v1; am = a4*4+1; }
                if (v2 > bm){ bm = v2; am = a4*4+2; }
                if (v3 > bm){ bm = v3; am = a4*4+3; }
                float4 v4; v4.x=v0; v4.y=v1; v4.z=v2; v4.w=v3;
                *(float4*)(op + a4*4) = v4;
            }
            if (ep > 0 && am > 0){
                const int ke = ep - 1;
                if (!((gta >> ke) & 1ull)){
                    gta |= 1ull << ke;
                    #pragma unroll
                    for (int a=0;a<36;a++) SG[a] += Wag2_s[ke][a];
                }
                const int ak = am - 1;
                if (!((garg >> ak) & 1ull)){
                    garg |= 1ull << ak;
                    #pragma unroll
                    for (int a=0;a<36;a++) SG[a] += Wag1_s[ak][a];
                }
            }
        }
    }
}

extern "C" void kernel_launch(void* const* d_in, const int* in_sizes, int n_in,
                              void* d_out, int out_size)
{
    const int*   ids  = (const int*)  d_in[0];
    const float* emb  = (const float*)d_in[1];
    const float* WihF = (const float*)d_in[2];
    const float* WhhF = (const float*)d_in[3];
    const float* bihF = (const float*)d_in[4];
    const float* bhhF = (const float*)d_in[5];
    const float* WihB = (const float*)d_in[6];
    const float* WhhB = (const float*)d_in[7];
    const float* bihB = (const float*)d_in[8];
    const float* bhhB = (const float*)d_in[9];
    const float* We   = (const float*)d_in[10];
    const float* be   = (const float*)d_in[11];
    const float* Wa   = (const float*)d_in[12];
    const float* ba   = (const float*)d_in[13];
    float* out    = (float*)d_out;
    float* evout  = out;
    float* argout = out + (long)NB*NL*NE;

    k1_zx<<<dim3(32, 32), 256>>>(ids, emb, WihF, WihB, bihF, bhhF, bihB, bhhB);
    k2_lstm<<<256, 256>>>(WhhF, WhhB);
    k3_pre<<<256, 128>>>(Wa, We, ba, be);
    k4_scan<<<16, 160>>>(Wa, We, evout, argout);
}

// round 6
// speedup vs baseline: 1.7163x; 1.7163x over previous
#include <cuda_runtime.h>
#include <math.h>

#define NB 16
#define NL 128
#define NH 256
#define ND 300
#define NE 34
#define NA 36

__device__ float d_zx[2][NL][NB][4*NH];
__device__ float d_hidden[NB][NL][2*NH];
__device__ float d_hcur[2][2][NB][NH];
__device__ float d_S [NB][NL][NA];
__device__ float d_T [NB][NL][NA];
__device__ float d_E0[NB][NL][NE];
__device__ int   d_evp[NB][NL];
__device__ unsigned g_grpD[2][8][32];   // per-dir group counters, 128B apart
__device__ unsigned g_rootD[2][32];     // per-dir root counters
__device__ unsigned g_genD[2][32];      // per-dir generation words

__device__ __forceinline__ float sigf(float x){ return 1.f/(1.f + expf(-x)); }

__device__ __forceinline__ unsigned long long ffma2(unsigned long long a,
        unsigned long long b, unsigned long long c){
    unsigned long long d;
    asm("fma.rn.f32x2 %0, %1, %2, %3;" : "=l"(d) : "l"(a), "l"(b), "l"(c));
    return d;
}
__device__ __forceinline__ float hsum2(unsigned long long v){
    unsigned lo, hi;
    asm("mov.b64 {%0,%1}, %2;" : "=r"(lo), "=r"(hi) : "l"(v));
    return __uint_as_float(lo) + __uint_as_float(hi);
}
__device__ __forceinline__ unsigned ordk(float v){
    unsigned u = __float_as_uint(v);
    return (u & 0x80000000u) ? ~u : (u | 0x80000000u);
}

// ============================================================================
// K1: zx = gather(emb, ids) @ Wih^T + (bih+bhh). Smem tiles in k-pair (f32x2)
// layout so every FMA is an FFMA2 with no packing.
// ============================================================================
__global__ void __launch_bounds__(256) k1_zx(const int* __restrict__ ids,
        const float* __restrict__ emb,
        const float* __restrict__ WihF, const float* __restrict__ WihB,
        const float* __restrict__ bihF, const float* __restrict__ bhhF,
        const float* __restrict__ bihB, const float* __restrict__ bhhB)
{
    __shared__ __align__(16) float2 As2[8][66];   // [k-pair][m]
    __shared__ __align__(16) float2 Bs2[8][66];   // [k-pair][n]
    __shared__ int ids_s[64];
    const int tid = threadIdx.x;
    const int m0 = blockIdx.y * 64;
    const int n0 = blockIdx.x * 64;
    if (tid < 64) ids_s[tid] = ids[m0 + tid];
    __syncthreads();
    const int lm = tid & 63;
    const int k4 = tid >> 6;     // 0..3
    const int ty = tid >> 4;     // 0..15
    const int tx = tid & 15;     // 0..15
    unsigned long long acc2[4][4];
    #pragma unroll
    for (int i=0;i<4;i++)
        #pragma unroll
        for (int j=0;j<4;j++) acc2[i][j] = 0ull;

    for (int kt = 0; kt < 19; kt++) {
        const int k0 = kt*16 + k4*4;
        {
            const int id = ids_s[lm];
            const float* src = emb + (long)id*ND + k0;
            float v0=0.f,v1=0.f,v2=0.f,v3=0.f;
            if (k0 + 3 < ND) { float4 t4 = *(const float4*)src; v0=t4.x;v1=t4.y;v2=t4.z;v3=t4.w; }
            else {
                if (k0+0 < ND) v0 = src[0];
                if (k0+1 < ND) v1 = src[1];
                if (k0+2 < ND) v2 = src[2];
            }
            As2[k4*2+0][lm] = make_float2(v0,v1);
            As2[k4*2+1][lm] = make_float2(v2,v3);
        }
        {
            const int n = n0 + lm;
            const float* wr = (n < 1024) ? (WihF + (long)n*ND) : (WihB + (long)(n-1024)*ND);
            const float* src = wr + k0;
            float v0=0.f,v1=0.f,v2=0.f,v3=0.f;
            if (k0 + 3 < ND) { float4 t4 = *(const float4*)src; v0=t4.x;v1=t4.y;v2=t4.z;v3=t4.w; }
            else {
                if (k0+0 < ND) v0 = src[0];
                if (k0+1 < ND) v1 = src[1];
                if (k0+2 < ND) v2 = src[2];
            }
            Bs2[k4*2+0][lm] = make_float2(v0,v1);
            Bs2[k4*2+1][lm] = make_float2(v2,v3);
        }
        __syncthreads();
        #pragma unroll
        for (int kp = 0; kp < 8; kp++) {
            const ulonglong2 a01 = *(const ulonglong2*)&As2[kp][ty*4];
            const ulonglong2 a23 = *(const ulonglong2*)&As2[kp][ty*4+2];
            const ulonglong2 b01 = *(const ulonglong2*)&Bs2[kp][tx*4];
            const ulonglong2 b23 = *(const ulonglong2*)&Bs2[kp][tx*4+2];
            const unsigned long long av[4] = {a01.x, a01.y, a23.x, a23.y};
            const unsigned long long bv[4] = {b01.x, b01.y, b23.x, b23.y};
            #pragma unroll
            for (int i=0;i<4;i++){
                #pragma unroll
                for (int j=0;j<4;j++) acc2[i][j] = ffma2(av[i], bv[j], acc2[i][j]);
            }
        }
        __syncthreads();
    }
    #pragma unroll
    for (int jj=0;jj<4;jj++){
        const int n = n0 + tx*4 + jj;
        const float bias = (n < 1024) ? (bihF[n] + bhhF[n]) : (bihB[n-1024] + bhhB[n-1024]);
        #pragma unroll
        for (int i=0;i<4;i++){
            const int m = m0 + ty*4 + i;
            const int bb = m >> 7, t = m & 127;
            const float v = hsum2(acc2[i][jj]) + bias;
            if (n < 1024) d_zx[0][t][bb][n]      = v;
            else          d_zx[1][t][bb][n-1024] = v;
        }
    }
}

// ============================================================================
// K2: persistent BiLSTM. 128 blocks (dir = bx>>6, 4 units) x 512 threads.
// Smem-resident W + staged h (proven structure), ffma2 dot, per-direction
// 8x8 tree barrier with monotonic generation counters (replay-safe).
// ============================================================================
__global__ void __launch_bounds__(512) k2_lstm(const float* __restrict__ WhhF,
                                               const float* __restrict__ WhhB)
{
    __shared__ __align__(16) float W_s[16][260];
    __shared__ __align__(16) float h_s[16][260];
    __shared__ float zp[16][16][8];
    const int tid = threadIdx.x;
    const int bx  = blockIdx.x;
    const int dir = bx >> 6;
    const int sub = bx & 63;
    const int u0  = sub * 4;
    const float* Whh = dir ? WhhB : WhhF;

    for (int idx = tid; idx < 16*256; idx += 512){
        const int rl = idx >> 8, k = idx & 255;
        const int rg = (rl >> 2) * 256 + u0 + (rl & 3);
        W_s[rl][k] = Whh[(long)rg*256 + k];
    }

    const int lane = tid & 31, w = tid >> 5;   // 16 warps
    const int bdot = lane & 15;
    const int rq   = (lane >> 4) + 2*(w & 1);  // 0..3
    const int kq   = w >> 1;                   // 0..7 (32-wide k slice)

    float creg = 0.f;
    const int cb = tid & 15, cu = (tid >> 4) & 3;   // gates thread (tid<64)

    const unsigned G0 = *(volatile unsigned*)&g_genD[dir][0];
    const int grp = sub >> 3;                        // 8 groups of 8 per dir
    __syncthreads();

    for (unsigned t = 0; t < NL; t++){
        const int xt = dir ? (NL-1-(int)t) : (int)t;
        const int wb = t & 1, rb = 1 - wb;

        // stage previous h into smem first (longest latency)
        if (t == 0){
            for (int idx = tid; idx < 16*256; idx += 512)
                h_s[idx >> 8][idx & 255] = 0.f;
        } else {
            const float4* hp = (const float4*)&d_hcur[dir][rb][0][0];
            for (int idx = tid; idx < 1024; idx += 512){
                float4 v = __ldcg(hp + idx);
                *(float4*)&h_s[idx >> 6][(idx*4) & 255] = v;
            }
        }
        // prefetch this step's zx for the gate phase
        float zx4[4];
        if (tid < 64){
            const float* zb = &d_zx[dir][xt][cb][0];
            #pragma unroll
            for (int g=0; g<4; g++) zx4[g] = __ldg(zb + g*256 + u0 + cu);
        }
        __syncthreads();

        // dot: 4 rows x 1 batch x 32 k per thread, ffma2
        const ulonglong2* hp2 = (const ulonglong2*)&h_s[bdot][kq*32];
        unsigned long long a2[4] = {0ull,0ull,0ull,0ull};
        #pragma unroll
        for (int i=0;i<8;i++){
            const ulonglong2 hu = hp2[i];
            #pragma unroll
            for (int rr=0;rr<4;rr++){
                const ulonglong2 wv = ((const ulonglong2*)&W_s[rq*4+rr][kq*32])[i];
                a2[rr] = ffma2(hu.x, wv.x, a2[rr]);
                a2[rr] = ffma2(hu.y, wv.y, a2[rr]);
            }
        }
        #pragma unroll
        for (int rr=0;rr<4;rr++) zp[rq*4+rr][bdot][kq] = hsum2(a2[rr]);
        __syncthreads();

        // gates
        if (tid < 64){
            float z[4];
            #pragma unroll
            for (int g=0; g<4; g++){
                const float* q = zp[g*4+cu][cb];
                z[g] = zx4[g] + (((q[0]+q[1]) + (q[2]+q[3])) + ((q[4]+q[5]) + (q[6]+q[7])));
            }
            creg = sigf(z[1])*creg + sigf(z[0])*tanhf(z[2]);
            const float h = sigf(z[3])*tanhf(creg);
            const int u = u0 + cu;
            __stcg(&d_hcur[dir][wb][cb][u], h);
            d_hidden[cb][xt][dir*NH + u] = h;
        }
        __syncthreads();

        // per-direction tree barrier (8 groups of 8), skip after last step
        if (t < NL-1){
            if (tid == 0){
                __threadfence();
                const unsigned want = G0 + t + 1u;
                unsigned* gen = &g_genD[dir][0];
                const unsigned p = atomicAdd(&g_grpD[dir][grp][0], 1u);
                if (p == G0*8u + t*8u + 7u){
                    const unsigned q = atomicAdd(&g_rootD[dir][0], 1u);
                    if (q == G0*8u + t*8u + 7u){
                        atomicExch(gen, want);
                    } else {
                        while ((int)(*(volatile unsigned*)gen - want) < 0) {}
                    }
                } else {
                    while ((int)(*(volatile unsigned*)gen - want) < 0) {}
                }
                __threadfence();
            }
            __syncthreads();
        }
    }
}

// ============================================================================
// K3: per-token static decode projections S, T, E0 (ffma2 dots).
// ============================================================================
__global__ void __launch_bounds__(128) k3_pre(const float* __restrict__ Wa,
        const float* __restrict__ We,
        const float* __restrict__ ba, const float* __restrict__ be)
{
    __shared__ __align__(16) float hid_s[8][516];
    const int tid = threadIdx.x;
    const int m0 = blockIdx.x * 8;
    const float* hbase = &d_hidden[0][0][0] + (long)m0 * 512;
    for (int idx = tid; idx < 8*512; idx += 128)
        hid_s[idx >> 9][idx & 511] = hbase[idx];
    __syncthreads();
    const int tok = tid >> 4, slot = tid & 15;
    const int m = m0 + tok;
    const float* hv = hid_s[tok];
    for (int cc = slot; cc < 106; cc += 16){
        if (cc < 72){
            const float* wr = Wa + (long)(cc < 36 ? cc : cc-36) * 1092 + (cc < 36 ? 0 : 512);
            const ulonglong2* wp = (const ulonglong2*)wr;
            const ulonglong2* hp = (const ulonglong2*)hv;
            unsigned long long s0 = 0ull, s1 = 0ull;
            #pragma unroll 4
            for (int k = 0; k < 128; k++){
                const ulonglong2 wv = wp[k];
                const ulonglong2 hu = hp[k];
                s0 = ffma2(hu.x, wv.x, s0);
                s1 = ffma2(hu.y, wv.y, s1);
            }
            float acc = hsum2(s0) + hsum2(s1);
            if (cc < 36) { acc += ba[cc]; (&d_S[0][0][0])[(long)m*36 + cc]      = acc; }
            else         {               (&d_T[0][0][0])[(long)m*36 + (cc-36)] = acc; }
        } else {
            const int e = cc - 72;
            const float* wr = We + (long)e * 545;
            float acc = 0.f;
            #pragma unroll 4
            for (int k = 0; k < 512; k += 4){
                acc = fmaf(hv[k+0], wr[k+0], acc);
                acc = fmaf(hv[k+1], wr[k+1], acc);
                acc = fmaf(hv[k+2], wr[k+2], acc);
                acc = fmaf(hv[k+3], wr[k+3], acc);
            }
            acc += be[e];
            (&d_E0[0][0][0])[(long)m*34 + e] = acc;
        }
    }
}

// ============================================================================
// K3b: sequential event scan. 16 blocks x 32 threads (one warp per batch).
// Pure register/warp chain; writes event logits + ev_pred to global.
// ============================================================================
__global__ void __launch_bounds__(32) k3b_event(const float* __restrict__ We,
        float* __restrict__ evout)
{
    __shared__ float Weg_s[33][34];
    const int lane = threadIdx.x;
    const int b = blockIdx.x;
    for (int idx = lane; idx < 33*34; idx += 32){
        const int k = idx / 34, e = idx % 34;
        Weg_s[k][e] = We[(long)e*545 + 512 + k];
    }
    __syncwarp();

    const float* E0b = &d_E0[b][0][0];
    float gtA = 0.f, gtB = 0.f;
    unsigned long long gtrg = 0ull;
    float e0a = __ldg(E0b + lane);
    float e0b = (lane < 2) ? __ldg(E0b + 32 + lane) : 0.f;

    for (int i = 0; i < NL; i++){
        float e0a_n = 0.f, e0b_n = 0.f;
        if (i < NL-1){
            e0a_n = __ldg(E0b + (i+1)*34 + lane);
            if (lane < 2) e0b_n = __ldg(E0b + (i+1)*34 + 32 + lane);
        }
        const float va = e0a + gtA;
        float vb = -3.0e38f;
        if (lane < 2) vb = e0b + gtB;
        evout[((long)b*NL + i)*NE + lane] = va;
        if (lane < 2) evout[((long)b*NL + i)*NE + 32 + lane] = vb;
        const unsigned ka = ordk(va);
        const unsigned mx = __reduce_max_sync(0xffffffffu, ka);
        const unsigned ball = __ballot_sync(0xffffffffu, ka == mx);
        const int am0 = __ffs(ball) - 1;
        float bv = __shfl_sync(0xffffffffu, va, am0);
        int ame = am0;
        const float v32 = __shfl_sync(0xffffffffu, vb, 0);
        const float v33 = __shfl_sync(0xffffffffu, vb, 1);
        if (v32 > bv){ bv = v32; ame = 32; }
        if (v33 > bv){ bv = v33; ame = 33; }
        int ne = 0;
        if (ame > 0 && !((gtrg >> (ame-1)) & 1ull)){ gtrg |= 1ull << (ame-1); ne = 1; }
        if (lane == 0) d_evp[b][i] = ame;
        if (ne){
            gtA += Weg_s[ame-1][lane];
            if (lane < 2) gtB += Weg_s[ame-1][32+lane];
        }
        e0a = e0a_n; e0b = e0b_n;
    }
}

// ============================================================================
// K4: arg decode, pure parallel consumer. 16 blocks x 128 threads (one per
// position j); event predictions preloaded — no spins, no block syncs in loop.
// ============================================================================
__global__ void __launch_bounds__(128) k4_scan(const float* __restrict__ Wa,
        float* __restrict__ argout)
{
    __shared__ __align__(16) float Ts[NL][NA];
    __shared__ float Wag1_s[35][36];
    __shared__ float Wag2_s[33][36];
    __shared__ int evp_s[NL];

    const int tid = threadIdx.x;
    const int b = blockIdx.x;
    for (int idx = tid; idx < NL*NA; idx += 128) (&Ts[0][0])[idx] = (&d_T[b][0][0])[idx];
    for (int idx = tid; idx < 35*36; idx += 128){
        const int k = idx / 36, a = idx % 36;
        Wag1_s[k][a] = Wa[(long)a*1092 + 1024 + k];
    }
    for (int idx = tid; idx < 33*36; idx += 128){
        const int k = idx / 36, a = idx % 36;
        Wag2_s[k][a] = Wa[(long)a*1092 + 1059 + k];
    }
    if (tid < NL) evp_s[tid] = d_evp[b][tid];

    const int j = tid;
    float SG[36];
    {
        const float4* sp = (const float4*)&d_S[b][j][0];
        #pragma unroll
        for (int q=0;q<9;q++){
            const float4 v = sp[q];
            SG[q*4+0]=v.x; SG[q*4+1]=v.y; SG[q*4+2]=v.z; SG[q*4+3]=v.w;
        }
    }
    unsigned long long garg = 0ull, gta = 0ull;
    __syncthreads();

    for (int i = 0; i < NL; i++){
        const int ep = evp_s[i];
        const float* Ti = &Ts[i][0];
        float* op = argout + (((long)b*NL + i)*NL + j)*NA;
        int am = 0; float bm = -1e30f;
        #pragma unroll
        for (int a4 = 0; a4 < 9; a4++){
            const float v0 = SG[a4*4+0] + Ti[a4*4+0];
            const float v1 = SG[a4*4+1] + Ti[a4*4+1];
            const float v2 = SG[a4*4+2] + Ti[a4*4+2];
            const float v3 = SG[a4*4+3] + Ti[a4*4+3];
            if (v0 > bm){ bm = v0; am = a4*4+0; }
            if (v1 > bm){ bm = v1; am = a4*4+1; }
            if (v2 > bm){ bm = v2; am = a4*4+2; }
            if (v3 > bm){ bm = v3; am = a4*4+3; }
            float4 v4; v4.x=v0; v4.y=v1; v4.z=v2; v4.w=v3;
            *(float4*)(op + a4*4) = v4;
        }
        if (ep > 0 && am > 0){
            const int ke = ep - 1;
            if (!((gta >> ke) & 1ull)){
                gta |= 1ull << ke;
                #pragma unroll
                for (int a=0;a<36;a++) SG[a] += Wag2_s[ke][a];
            }
            const int ak = am - 1;
            if (!((garg >> ak) & 1ull)){
                garg |= 1ull << ak;
                #pragma unroll
                for (int a=0;a<36;a++) SG[a] += Wag1_s[ak][a];
            }
        }
    }
}

extern "C" void kernel_launch(void* const* d_in, const int* in_sizes, int n_in,
                              void* d_out, int out_size)
{
    const int*   ids  = (const int*)  d_in[0];
    const float* emb  = (const float*)d_in[1];
    const float* WihF = (const float*)d_in[2];
    const float* WhhF = (const float*)d_in[3];
    const float* bihF = (const float*)d_in[4];
    const float* bhhF = (const float*)d_in[5];
    const float* WihB = (const float*)d_in[6];
    const float* WhhB = (const float*)d_in[7];
    const float* bihB = (const float*)d_in[8];
    const float* bhhB = (const float*)d_in[9];
    const float* We   = (const float*)d_in[10];
    const float* be   = (const float*)d_in[11];
    const float* Wa   = (const float*)d_in[12];
    const float* ba   = (const float*)d_in[13];
    float* out    = (float*)d_out;
    float* evout  = out;
    float* argout = out + (long)NB*NL*NE;

    k1_zx<<<dim3(32, 32), 256>>>(ids, emb, WihF, WihB, bihF, bhhF, bihB, bhhB);
    k2_lstm<<<128, 512>>>(WhhF, WhhB);
    k3_pre<<<256, 128>>>(Wa, We, ba, be);
    k3b_event<<<16, 32>>>(We, evout);
    k4_scan<<<16, 128>>>(Wa, argout);
}

// round 8
// speedup vs baseline: 1.9605x; 1.1423x over previous
#include <cuda_runtime.h>
#include <math.h>

#define NB 16
#define NL 128
#define NH 256
#define ND 300
#define NE 34
#define NA 36

__device__ float d_zx[2][NL][NB][4*NH];
__device__ float d_hidden[NB][NL][2*NH];
__device__ float d_hcur[2][2][NB][NH];
__device__ float d_S [NB][NL][NA];
__device__ float d_T [NB][NL][NA];
__device__ float d_E0[NB][NL][NE];
__device__ int   d_evp[NB][NL];
__device__ unsigned g_slot[2][64][32];   // per-block completion counters, 128B apart

__device__ __forceinline__ float sigf(float x){ return 1.f/(1.f + expf(-x)); }
__device__ __forceinline__ unsigned ordk(float v){
    unsigned u = __float_as_uint(v);
    return (u & 0x80000000u) ? ~u : (u | 0x80000000u);
}
// un-hoistable volatile global load for spin-polling
__device__ __forceinline__ unsigned ldvol(const unsigned* p){
    unsigned v;
    asm volatile("ld.volatile.global.u32 %0, [%1];" : "=r"(v) : "l"(p));
    return v;
}

// ============================================================================
// K1: zx = gather(emb, ids) @ Wih^T + (bih+bhh), both directions fused.
// ============================================================================
__global__ void __launch_bounds__(256) k1_zx(const int* __restrict__ ids,
        const float* __restrict__ emb,
        const float* __restrict__ WihF, const float* __restrict__ WihB,
        const float* __restrict__ bihF, const float* __restrict__ bhhF,
        const float* __restrict__ bihB, const float* __restrict__ bhhB)
{
    __shared__ __align__(16) float As[16][68];
    __shared__ __align__(16) float Bs[16][68];
    __shared__ int ids_s[64];
    const int tid = threadIdx.x;
    const int m0 = blockIdx.y * 64;
    const int n0 = blockIdx.x * 64;
    if (tid < 64) ids_s[tid] = ids[m0 + tid];
    __syncthreads();
    const int lm = tid & 63;
    const int k4 = tid >> 6;
    const int ty = tid >> 4;
    const int tx = tid & 15;
    float acc[4][4];
    #pragma unroll
    for (int i=0;i<4;i++){ acc[i][0]=0.f; acc[i][1]=0.f; acc[i][2]=0.f; acc[i][3]=0.f; }

    for (int kt = 0; kt < 19; kt++) {
        const int k0 = kt*16 + k4*4;
        {
            const int id = ids_s[lm];
            const float* src = emb + (long)id*ND + k0;
            float v0=0.f,v1=0.f,v2=0.f,v3=0.f;
            if (k0 + 3 < ND) { float4 t4 = *(const float4*)src; v0=t4.x;v1=t4.y;v2=t4.z;v3=t4.w; }
            else {
                if (k0+0 < ND) v0 = src[0];
                if (k0+1 < ND) v1 = src[1];
                if (k0+2 < ND) v2 = src[2];
            }
            As[k4*4+0][lm]=v0; As[k4*4+1][lm]=v1; As[k4*4+2][lm]=v2; As[k4*4+3][lm]=v3;
        }
        {
            const int n = n0 + lm;
            const float* wr = (n < 1024) ? (WihF + (long)n*ND) : (WihB + (long)(n-1024)*ND);
            const float* src = wr + k0;
            float v0=0.f,v1=0.f,v2=0.f,v3=0.f;
            if (k0 + 3 < ND) { float4 t4 = *(const float4*)src; v0=t4.x;v1=t4.y;v2=t4.z;v3=t4.w; }
            else {
                if (k0+0 < ND) v0 = src[0];
                if (k0+1 < ND) v1 = src[1];
                if (k0+2 < ND) v2 = src[2];
            }
            Bs[k4*4+0][lm]=v0; Bs[k4*4+1][lm]=v1; Bs[k4*4+2][lm]=v2; Bs[k4*4+3][lm]=v3;
        }
        __syncthreads();
        #pragma unroll
        for (int kk = 0; kk < 16; kk++) {
            const float4 a4 = *(const float4*)&As[kk][ty*4];
            const float4 b4 = *(const float4*)&Bs[kk][tx*4];
            const float av[4] = {a4.x,a4.y,a4.z,a4.w};
            const float bv[4] = {b4.x,b4.y,b4.z,b4.w};
            #pragma unroll
            for (int i=0;i<4;i++){
                #pragma unroll
                for (int jj=0;jj<4;jj++) acc[i][jj] = fmaf(av[i], bv[jj], acc[i][jj]);
            }
        }
        __syncthreads();
    }
    #pragma unroll
    for (int jj=0;jj<4;jj++){
        const int n = n0 + tx*4 + jj;
        const float bias = (n < 1024) ? (bihF[n] + bhhF[n]) : (bihB[n-1024] + bhhB[n-1024]);
        #pragma unroll
        for (int i=0;i<4;i++){
            const int m = m0 + ty*4 + i;
            const int bb = m >> 7, t = m & 127;
            const float v = acc[i][jj] + bias;
            if (n < 1024) d_zx[0][t][bb][n]      = v;
            else          d_zx[1][t][bb][n-1024] = v;
        }
    }
}

// ============================================================================
// K2: persistent BiLSTM. 128 blocks (dir = bx>>6, 4 units) x 512 threads.
// Store-based distributed barrier (no atomics). Arrival = st.cg to a private
// padded slot; detection = warp 0 polls all 64 slots with VOLATILE loads.
// Monotonic counters -> graph-replay safe.
// ============================================================================
__global__ void __launch_bounds__(512) k2_lstm(const float* __restrict__ WhhF,
                                               const float* __restrict__ WhhB)
{
    __shared__ __align__(16) float W_s[16][260];
    __shared__ __align__(16) float h_s[16][260];
    __shared__ float zp[16][16][8];
    const int tid = threadIdx.x;
    const int bx  = blockIdx.x;
    const int dir = bx >> 6;
    const int sub = bx & 63;
    const int u0  = sub * 4;
    const float* Whh = dir ? WhhB : WhhF;

    for (int idx = tid; idx < 16*256; idx += 512){
        const int rl = idx >> 8, k = idx & 255;
        const int rg = (rl >> 2) * 256 + u0 + (rl & 3);
        W_s[rl][k] = Whh[(long)rg*256 + k];
    }

    const int lane = tid & 31, w = tid >> 5;   // 16 warps
    const int bdot = lane & 15;
    const int rq   = (lane >> 4) + 2*(w & 1);  // 0..3
    const int kq   = w >> 1;                   // 0..7 (32-wide k slice)

    float creg = 0.f;
    const int cb = tid & 15, cu = (tid >> 4) & 3;   // gates thread (tid<64)

    // base generation: my own slot (nobody else writes it)
    const unsigned G0 = ldvol(&g_slot[dir][sub][0]);
    const unsigned* const slots = &g_slot[dir][0][0];
    __syncthreads();

    for (unsigned t = 0; t < NL; t++){
        const int xt = dir ? (NL-1-(int)t) : (int)t;
        const int wb = t & 1, rb = 1 - wb;

        // prefetch this step's zx (static input — overlaps the barrier wait)
        float zx4[4];
        if (tid < 64){
            const float* zb = &d_zx[dir][xt][cb][0];
            #pragma unroll
            for (int g=0; g<4; g++) zx4[g] = __ldg(zb + g*256 + u0 + cu);
        }

        // wait for all blocks of this direction to have published step t
        if (t > 0){
            if (tid < 32){
                const unsigned want = G0 + t;
                while (true){
                    const unsigned v0 = ldvol(slots + lane*32);
                    const unsigned v1 = ldvol(slots + (lane+32)*32);
                    const bool ok = ((int)(v0 - want) >= 0) && ((int)(v1 - want) >= 0);
                    if (__all_sync(0xffffffffu, ok)) break;
                    __nanosleep(32);
                }
                __threadfence();
            }
            __syncthreads();
        }

        // stage previous h into smem
        if (t == 0){
            for (int idx = tid; idx < 16*256; idx += 512)
                h_s[idx >> 8][idx & 255] = 0.f;
        } else {
            const float4* hp = (const float4*)&d_hcur[dir][rb][0][0];
            for (int idx = tid; idx < 1024; idx += 512){
                float4 v = __ldcg(hp + idx);
                *(float4*)&h_s[idx >> 6][(idx*4) & 255] = v;
            }
        }
        __syncthreads();

        // dot: 4 rows x 1 batch x 32 k per thread
        float4 hreg[8];
        #pragma unroll
        for (int i=0;i<8;i++) hreg[i] = *(const float4*)&h_s[bdot][kq*32 + i*4];
        float acc[4] = {0.f,0.f,0.f,0.f};
        #pragma unroll
        for (int i=0;i<8;i++){
            const float4 hv = hreg[i];
            #pragma unroll
            for (int rr=0;rr<4;rr++){
                const float4 wv = *(const float4*)&W_s[rq*4+rr][kq*32 + i*4];
                float a = acc[rr];
                a = fmaf(hv.x, wv.x, a);
                a = fmaf(hv.y, wv.y, a);
                a = fmaf(hv.z, wv.z, a);
                a = fmaf(hv.w, wv.w, a);
                acc[rr] = a;
            }
        }
        #pragma unroll
        for (int rr=0;rr<4;rr++) zp[rq*4+rr][bdot][kq] = acc[rr];
        __syncthreads();

        // gates
        if (tid < 64){
            float z[4];
            #pragma unroll
            for (int g=0; g<4; g++){
                const float* q = zp[g*4+cu][cb];
                z[g] = zx4[g] + (((q[0]+q[1]) + (q[2]+q[3])) + ((q[4]+q[5]) + (q[6]+q[7])));
            }
            creg = sigf(z[1])*creg + sigf(z[0])*tanhf(z[2]);
            const float h = sigf(z[3])*tanhf(creg);
            const int u = u0 + cu;
            __stcg(&d_hcur[dir][wb][cb][u], h);
            d_hidden[cb][xt][dir*NH + u] = h;
        }
        __syncthreads();

        // publish arrival for step t (skip last step; counters stay consistent)
        if (t < NL-1){
            if (tid == 0){
                __threadfence();
                asm volatile("st.volatile.global.u32 [%0], %1;"
                             :: "l"(&g_slot[dir][sub][0]), "r"(G0 + t + 1u));
            }
        }
    }
}

// ============================================================================
// K3: per-token static decode projections S, T, E0.
// ============================================================================
__global__ void __launch_bounds__(128) k3_pre(const float* __restrict__ Wa,
        const float* __restrict__ We,
        const float* __restrict__ ba, const float* __restrict__ be)
{
    __shared__ __align__(16) float hid_s[8][516];
    const int tid = threadIdx.x;
    const int m0 = blockIdx.x * 8;
    const float* hbase = &d_hidden[0][0][0] + (long)m0 * 512;
    for (int idx = tid; idx < 8*512; idx += 128)
        hid_s[idx >> 9][idx & 511] = hbase[idx];
    __syncthreads();
    const int tok = tid >> 4, slot = tid & 15;
    const int m = m0 + tok;
    const float* hv = hid_s[tok];
    for (int cc = slot; cc < 106; cc += 16){
        float acc = 0.f;
        if (cc < 72){
            const float* wr = Wa + (long)(cc < 36 ? cc : cc-36) * 1092 + (cc < 36 ? 0 : 512);
            #pragma unroll 4
            for (int k = 0; k < 512; k += 4){
                const float4 w4 = *(const float4*)(wr + k);
                const float4 h4 = *(const float4*)(hv + k);
                acc = fmaf(h4.x, w4.x, acc);
                acc = fmaf(h4.y, w4.y, acc);
                acc = fmaf(h4.z, w4.z, acc);
                acc = fmaf(h4.w, w4.w, acc);
            }
            if (cc < 36) { acc += ba[cc]; (&d_S[0][0][0])[(long)m*36 + cc]      = acc; }
            else         {               (&d_T[0][0][0])[(long)m*36 + (cc-36)] = acc; }
        } else {
            const int e = cc - 72;
            const float* wr = We + (long)e * 545;
            #pragma unroll 4
            for (int k = 0; k < 512; k += 4){
                acc = fmaf(hv[k+0], wr[k+0], acc);
                acc = fmaf(hv[k+1], wr[k+1], acc);
                acc = fmaf(hv[k+2], wr[k+2], acc);
                acc = fmaf(hv[k+3], wr[k+3], acc);
            }
            acc += be[e];
            (&d_E0[0][0][0])[(long)m*34 + e] = acc;
        }
    }
}

// ============================================================================
// K3b: sequential event scan. 16 blocks x 32 threads (one warp per batch).
// ============================================================================
__global__ void __launch_bounds__(32) k3b_event(const float* __restrict__ We,
        float* __restrict__ evout)
{
    __shared__ float Weg_s[33][34];
    const int lane = threadIdx.x;
    const int b = blockIdx.x;
    for (int idx = lane; idx < 33*34; idx += 32){
        const int k = idx / 34, e = idx % 34;
        Weg_s[k][e] = We[(long)e*545 + 512 + k];
    }
    __syncwarp();

    const float* E0b = &d_E0[b][0][0];
    float gtA = 0.f, gtB = 0.f;
    unsigned long long gtrg = 0ull;
    const int tail = (lane < 2) ? (32 + lane) : 33;
    float e0a = __ldg(E0b + lane);
    float e0b = __ldg(E0b + tail);

    for (int i = 0; i < NL; i++){
        float e0a_n = 0.f, e0b_n = 0.f;
        if (i < NL-1){
            e0a_n = __ldg(E0b + (i+1)*34 + lane);
            e0b_n = __ldg(E0b + (i+1)*34 + tail);
        }
        const float va = e0a + gtA;
        const float vb = (lane < 2) ? (e0b + gtB) : -3.0e38f;
        evout[((long)b*NL + i)*NE + lane] = va;
        if (lane < 2) evout[((long)b*NL + i)*NE + 32 + lane] = vb;
        const unsigned ka = ordk(va);
        const unsigned mx = __reduce_max_sync(0xffffffffu, ka);
        const unsigned ball = __ballot_sync(0xffffffffu, ka == mx);
        const int am0 = __ffs(ball) - 1;
        float bv = __shfl_sync(0xffffffffu, va, am0);
        int ame = am0;
        const float v32 = __shfl_sync(0xffffffffu, vb, 0);
        const float v33 = __shfl_sync(0xffffffffu, vb, 1);
        if (v32 > bv){ bv = v32; ame = 32; }
        if (v33 > bv){ bv = v33; ame = 33; }
        int ne = 0;
        if (ame > 0 && !((gtrg >> (ame-1)) & 1ull)){ gtrg |= 1ull << (ame-1); ne = 1; }
        if (lane == 0) d_evp[b][i] = ame;
        if (ne){
            gtA += Weg_s[ame-1][lane];
            if (lane < 2) gtB += Weg_s[ame-1][32+lane];
        }
        e0a = e0a_n; e0b = e0b_n;
    }
}

// ============================================================================
// K4: arg decode, pure parallel consumer. 16 blocks x 128 threads.
// ============================================================================
__global__ void __launch_bounds__(128) k4_scan(const float* __restrict__ Wa,
        float* __restrict__ argout)
{
    __shared__ __align__(16) float Ts[NL][NA];
    __shared__ float Wag1_s[35][36];
    __shared__ float Wag2_s[33][36];
    __shared__ int evp_s[NL];

    const int tid = threadIdx.x;
    const int b = blockIdx.x;
    for (int idx = tid; idx < NL*NA; idx += 128) (&Ts[0][0])[idx] = (&d_T[b][0][0])[idx];
    for (int idx = tid; idx < 35*36; idx += 128){
        const int k = idx / 36, a = idx % 36;
        Wag1_s[k][a] = Wa[(long)a*1092 + 1024 + k];
    }
    for (int idx = tid; idx < 33*36; idx += 128){
        const int k = idx / 36, a = idx % 36;
        Wag2_s[k][a] = Wa[(long)a*1092 + 1059 + k];
    }
    if (tid < NL) evp_s[tid] = d_evp[b][tid];

    const int j = tid;
    float SG[36];
    {
        const float4* sp = (const float4*)&d_S[b][j][0];
        #pragma unroll
        for (int q=0;q<9;q++){
            const float4 v = sp[q];
            SG[q*4+0]=v.x; SG[q*4+1]=v.y; SG[q*4+2]=v.z; SG[q*4+3]=v.w;
        }
    }
    unsigned long long garg = 0ull, gta = 0ull;
    __syncthreads();

    for (int i = 0; i < NL; i++){
        const int ep = evp_s[i];
        const float* Ti = &Ts[i][0];
        float* op = argout + (((long)b*NL + i)*NL + j)*NA;
        int am = 0; float bm = -1e30f;
        #pragma unroll
        for (int a4 = 0; a4 < 9; a4++){
            const float v0 = SG[a4*4+0] + Ti[a4*4+0];
            const float v1 = SG[a4*4+1] + Ti[a4*4+1];
            const float v2 = SG[a4*4+2] + Ti[a4*4+2];
            const float v3 = SG[a4*4+3] + Ti[a4*4+3];
            if (v0 > bm){ bm = v0; am = a4*4+0; }
            if (v1 > bm){ bm = v1; am = a4*4+1; }
            if (v2 > bm){ bm = v2; am = a4*4+2; }
            if (v3 > bm){ bm = v3; am = a4*4+3; }
            float4 v4; v4.x=v0; v4.y=v1; v4.z=v2; v4.w=v3;
            *(float4*)(op + a4*4) = v4;
        }
        if (ep > 0 && am > 0){
            const int ke = ep - 1;
            if (!((gta >> ke) & 1ull)){
                gta |= 1ull << ke;
                #pragma unroll
                for (int a=0;a<36;a++) SG[a] += Wag2_s[ke][a];
            }
            const int ak = am - 1;
            if (!((garg >> ak) & 1ull)){
                garg |= 1ull << ak;
                #pragma unroll
                for (int a=0;a<36;a++) SG[a] += Wag1_s[ak][a];
            }
        }
    }
}

extern "C" void kernel_launch(void* const* d_in, const int* in_sizes, int n_in,
                              void* d_out, int out_size)
{
    const int*   ids  = (const int*)  d_in[0];
    const float* emb  = (const float*)d_in[1];
    const float* WihF = (const float*)d_in[2];
    const float* WhhF = (const float*)d_in[3];
    const float* bihF = (const float*)d_in[4];
    const float* bhhF = (const float*)d_in[5];
    const float* WihB = (const float*)d_in[6];
    const float* WhhB = (const float*)d_in[7];
    const float* bihB = (const float*)d_in[8];
    const float* bhhB = (const float*)d_in[9];
    const float* We   = (const float*)d_in[10];
    const float* be   = (const float*)d_in[11];
    const float* Wa   = (const float*)d_in[12];
    const float* ba   = (const float*)d_in[13];
    float* out    = (float*)d_out;
    float* evout  = out;
    float* argout = out + (long)NB*NL*NE;

    k1_zx<<<dim3(32, 32), 256>>>(ids, emb, WihF, WihB, bihF, bhhF, bihB, bhhB);
    k2_lstm<<<128, 512>>>(WhhF, WhhB);
    k3_pre<<<256, 128>>>(Wa, We, ba, be);
    k3b_event<<<16, 32>>>(We, evout);
    k4_scan<<<16, 128>>>(Wa, argout);
}